// round 4
// baseline (speedup 1.0000x reference)
#include <cuda_runtime.h>
#include <cuda_fp16.h>
#include <cstdint>

// ==========================================================================
// LSTM (relu candidate/output) + linear head via mma.sync m16n8k16 fp16
// B=65536, T=12, F=1, H=128.  CTA = 128 batch rows, 512 threads, grid 512.
// R4: xz+bias folded into MMA (K=144), contiguous h2 writeback, unroll 2.
// ==========================================================================

#define TT       12
#define HH       128
#define GG       512
#define MTILE    128
#define NTHREADS 512
#define KDIM     144                     // 128 h + x + 1 + 14 zero-pad
#define PADK     152                     // halfs per row (144 data + 8 pad)
#define ROWB     (PADK * 2)              // 304 bytes
#define WPR      (ROWB / 4)              // 76 words per row

// ---- shared memory layout (bytes) ----
#define BT_OFF   0
#define BT_BYTES (GG * ROWB)             // 155648 : Rext^T fp16 [n_perm][k_perm]
#define A_OFF    (BT_OFF + BT_BYTES)     // h/x state fp16 [row][k_perm]
#define A_BYTES  (MTILE * ROWB)          // 38912
#define WD_OFF   (A_OFF + A_BYTES)       // float[128]
#define XS_OFF   (WD_OFF + 512)          // float[128*12] x staged
#define RED_OFF  (XS_OFF + MTILE*TT*4)   // float[128*8] head partials
#define SMEM_TOTAL (RED_OFF + MTILE*8*4) // 205312

__device__ __forceinline__ uint32_t s2u(const void* p) {
    uint32_t a;
    asm("{ .reg .u64 t; cvta.to.shared.u64 t, %1; cvt.u32.u64 %0, t; }" : "=r"(a) : "l"(p));
    return a;
}

#define LDSM4(r0, r1, r2, r3, addr) \
    asm volatile("ldmatrix.sync.aligned.m8n8.x4.shared.b16 {%0,%1,%2,%3}, [%4];" \
                 : "=r"(r0), "=r"(r1), "=r"(r2), "=r"(r3) : "r"(addr))

#define MMA16816(d0, d1, d2, d3, a0, a1, a2, a3, b0, b1) \
    asm volatile("mma.sync.aligned.m16n8k16.row.col.f32.f16.f16.f32 " \
                 "{%0,%1,%2,%3}, {%4,%5,%6,%7}, {%8,%9}, {%0,%1,%2,%3};" \
                 : "+f"(d0), "+f"(d1), "+f"(d2), "+f"(d3) \
                 : "r"(a0), "r"(a1), "r"(a2), "r"(a3), "r"(b0), "r"(b1))

__device__ __forceinline__ float sigmoid_f(float v) {
    float e, r;
    asm("ex2.approx.f32 %0, %1;" : "=f"(e) : "f"(-1.4426950408889634f * v));
    asm("rcp.approx.f32 %0, %1;" : "=f"(r) : "f"(1.0f + e));
    return r;
}

__global__ __launch_bounds__(NTHREADS, 1)
void lstm_kernel(const float* __restrict__ x, const float* __restrict__ kern,
                 const float* __restrict__ rk, const float* __restrict__ bias,
                 const float* __restrict__ Wd, const float* __restrict__ bd,
                 float* __restrict__ out) {
    extern __shared__ char smem[];
    const uint32_t base = s2u(smem);
    const int tid  = threadIdx.x;
    const int lane = tid & 31;
    const int wid  = tid >> 5;
    const int m    = wid >> 1;       // m-tile (16 rows) 0..7
    const int half = wid & 1;        // N-half
    const int t4   = lane >> 2;      // 0..7
    const int j    = lane & 3;       // 0..3
    const int r_lo = 16 * m + t4;
    const int r_hi = r_lo + 8;
    const int b0   = blockIdx.x * MTILE;

    __half* bt = (__half*)(smem + BT_OFF);
    float*  wd = (float*)(smem + WD_OFF);
    float*  xs = (float*)(smem + XS_OFF);
    float*  red = (float*)(smem + RED_OFF);

    // ---- init ----
    // zero B (covers zero-pad k cols 130..143 + row pad)
    for (int i = tid; i < BT_BYTES / 4; i += NTHREADS)
        ((uint32_t*)(smem + BT_OFF))[i] = 0u;
    // zero A; word 64 of each row = (k128,k129) = (x_0, 1.0)
    for (int i = tid; i < A_BYTES / 4; i += NTHREADS) {
        int row = i / WPR, w = i - row * WPR;
        uint32_t v = 0u;
        if (w == 64) {
            __half2 p = __floats2half2_rn(x[(size_t)(b0 + row) * TT], 1.0f);
            v = *(uint32_t*)&p;
        }
        ((uint32_t*)(smem + A_OFF))[i] = v;
    }
    for (int i = tid; i < MTILE * TT; i += NTHREADS) xs[i] = x[(size_t)b0 * TT + i];
    if (tid < HH) wd[tid] = Wd[tid];
    __syncthreads();   // B zeroing complete before scattered fill

    // n-perm: unit u, gate g -> n = 16*(u/4) + 8*(g/2) + 2*(u%4) + (g&1)
    // k-perm: h-index ks -> kk = (ks&3)*32 + (ks>>2)   (thread j's units contiguous)
    for (int i = tid; i < HH * GG; i += NTHREADS) {
        int ks = i >> 9, col = i & 511;
        int u = col & 127, g = col >> 7;
        int n = 16 * (u >> 2) + 8 * (g >> 1) + 2 * (u & 3) + (g & 1);
        int kk = (ks & 3) * 32 + (ks >> 2);
        bt[n * PADK + kk] = __float2half(rk[i]);
    }
    for (int col = tid; col < GG; col += NTHREADS) {
        int u = col & 127, g = col >> 7;
        int n = 16 * (u >> 2) + 8 * (g >> 1) + 2 * (u & 3) + (g & 1);
        bt[n * PADK + 128] = __float2half(kern[col]);
        bt[n * PADK + 129] = __float2half(bias[col]);
    }
    __syncthreads();

    // ldmatrix lane addressing: row = lane%16, +16B col offset for lanes 16-31
    const uint32_t lrow = (uint32_t)((lane & 7) + (lane & 8));
    const uint32_t lcol = (uint32_t)((lane >> 4) << 4);
    const uint32_t a_base  = base + A_OFF  + (16u * m + lrow) * ROWB + lcol;
    const uint32_t bt_base = base + BT_OFF + ((uint32_t)half * 256u + lrow) * ROWB + lcol;
    // h writeback: rows r_lo/r_hi, bytes [64j + 32*half, +32)
    char* st_lo = smem + A_OFF + r_lo * ROWB + 64 * j + 32 * half;
    char* st_hi = smem + A_OFF + r_hi * ROWB + 64 * j + 32 * half;

    float c[32];
#pragma unroll
    for (int i = 0; i < 32; i++) c[i] = 0.0f;
    float ps_lo = 0.0f, ps_hi = 0.0f;
    const int bar_id = m + 1;

#pragma unroll 1
    for (int t = 0; t < TT; t++) {
        asm volatile("bar.sync %0, %1;" :: "r"(bar_id), "n"(64) : "memory");  // A ready

        uint32_t a[9][4];
#pragma unroll
        for (int kb = 0; kb < 9; kb++)
            LDSM4(a[kb][0], a[kb][1], a[kb][2], a[kb][3], a_base + kb * 32u);

        asm volatile("bar.sync %0, %1;" :: "r"(bar_id), "n"(64) : "memory");  // A consumed

        uint32_t hlo2[8], hhi2[8];
        float hp_lo = 0.f, hp_hi = 0.f;

#pragma unroll 2
        for (int pp = 0; pp < 16; pp++) {
            float d[8];
#pragma unroll
            for (int q = 0; q < 8; q++) d[q] = 0.0f;
            const uint32_t bta = bt_base + (uint32_t)pp * (16u * ROWB);
#pragma unroll
            for (int kb = 0; kb < 9; kb++) {
                uint32_t bq0, bq1, bq2, bq3;
                LDSM4(bq0, bq1, bq2, bq3, bta + kb * 32u);
                MMA16816(d[0], d[1], d[2], d[3], a[kb][0], a[kb][1], a[kb][2], a[kb][3], bq0, bq2);
                MMA16816(d[4], d[5], d[6], d[7], a[kb][0], a[kb][1], a[kb][2], a[kb][3], bq1, bq3);
            }
            // d = full pre-activation z.  lo: d0=i d1=f d4=g d5=o ; hi: d2 d3 d6 d7
            float ig = sigmoid_f(d[0]), fg = sigmoid_f(d[1]), og = sigmoid_f(d[5]);
            float cn = fmaf(fg, c[2 * pp], ig * fmaxf(d[4], 0.0f));
            c[2 * pp] = cn;
            float h_lo = og * fmaxf(cn, 0.0f);

            ig = sigmoid_f(d[2]); fg = sigmoid_f(d[3]); og = sigmoid_f(d[7]);
            float cn2 = fmaf(fg, c[2 * pp + 1], ig * fmaxf(d[6], 0.0f));
            c[2 * pp + 1] = cn2;
            float h_hi = og * fmaxf(cn2, 0.0f);

            if (pp & 1) {
                __half2 plo = __floats2half2_rn(hp_lo, h_lo);
                __half2 phi = __floats2half2_rn(hp_hi, h_hi);
                hlo2[pp >> 1] = *(uint32_t*)&plo;
                hhi2[pp >> 1] = *(uint32_t*)&phi;
            } else {
                hp_lo = h_lo; hp_hi = h_hi;
            }
            if (t == TT - 1) {
                const int u = 4 * (half * 16 + pp) + j;
                ps_lo = fmaf(h_lo, wd[u], ps_lo);
                ps_hi = fmaf(h_hi, wd[u], ps_hi);
            }
        }

        // contiguous fp16 h writeback: 2 x 16B per row
        *(uint4*)(st_lo)      = make_uint4(hlo2[0], hlo2[1], hlo2[2], hlo2[3]);
        *(uint4*)(st_lo + 16) = make_uint4(hlo2[4], hlo2[5], hlo2[6], hlo2[7]);
        *(uint4*)(st_hi)      = make_uint4(hhi2[0], hhi2[1], hhi2[2], hhi2[3]);
        *(uint4*)(st_hi + 16) = make_uint4(hhi2[4], hhi2[5], hhi2[6], hhi2[7]);

        // x for step t+1 (k=128,129), one designated thread per row
        if (half == 0 && j == 0 && t + 1 < TT) {
            __half2 plo = __floats2half2_rn(xs[r_lo * TT + t + 1], 1.0f);
            __half2 phi = __floats2half2_rn(xs[r_hi * TT + t + 1], 1.0f);
            *(uint32_t*)(smem + A_OFF + r_lo * ROWB + 256) = *(uint32_t*)&plo;
            *(uint32_t*)(smem + A_OFF + r_hi * ROWB + 256) = *(uint32_t*)&phi;
        }
    }

    // ---- output head: y = h_T . Wd + bd ----
    red[r_lo * 8 + half * 4 + j] = ps_lo;
    red[r_hi * 8 + half * 4 + j] = ps_hi;
    __syncthreads();
    if (tid < MTILE) {
        const float* p = red + tid * 8;
        float s = ((p[0] + p[1]) + (p[2] + p[3])) + ((p[4] + p[5]) + (p[6] + p[7]));
        out[b0 + tid] = s + bd[0];
    }
}

extern "C" void kernel_launch(void* const* d_in, const int* in_sizes, int n_in,
                              void* d_out, int out_size) {
    const float* x    = (const float*)d_in[0];
    const float* kern = (const float*)d_in[1];
    const float* rk   = (const float*)d_in[2];
    const float* bias = (const float*)d_in[3];
    const float* Wd   = (const float*)d_in[4];
    const float* bd   = (const float*)d_in[5];
    float* out = (float*)d_out;

    int B = in_sizes[0] / TT;        // 65536
    int grid = B / MTILE;            // 512

    cudaFuncSetAttribute(lstm_kernel, cudaFuncAttributeMaxDynamicSharedMemorySize, SMEM_TOTAL);
    lstm_kernel<<<grid, NTHREADS, SMEM_TOTAL>>>(x, kern, rk, bias, Wd, bd, out);
}

// round 5
// speedup vs baseline: 1.1396x; 1.1396x over previous
#include <cuda_runtime.h>
#include <cuda_fp16.h>
#include <cstdint>

// ==========================================================================
// LSTM (relu candidate/output) + linear head via mma.sync m16n8k16 fp16
// B=65536, T=12, F=1, H=128.  CTA = 128 batch rows, 512 threads, grid 512.
// R5: R3 base (K=128, fp32 x/bias tables) + tanh-based sigmoid (1 MUFU)
//     + k-permuted contiguous h writeback + pp unroll 2.
// ==========================================================================

#define TT       12
#define HH       128
#define GG       512
#define MTILE    128
#define NTHREADS 512
#define PADK     136                     // halfs per row (128 data + 8 pad)
#define ROWB     (PADK * 2)              // 272 bytes

// ---- shared memory layout (bytes) ----
#define BT_OFF   0
#define BT_BYTES (GG * ROWB)             // 139264 : R^T fp16 [n_perm][k_perm]
#define A_OFF    (BT_OFF + BT_BYTES)     // h state fp16 [row][k_perm]
#define A_BYTES  (MTILE * ROWB)          // 34816
#define KP_OFF   (A_OFF + A_BYTES)       // float4[128]  kernel per unit (i,f,g,o)
#define BP_OFF   (KP_OFF + 2048)         // float4[128]  bias per unit
#define WD_OFF   (BP_OFF + 2048)         // float[128]
#define XS_OFF   (WD_OFF + 512)          // float[128*12] x staged
#define RED_OFF  (XS_OFF + MTILE*TT*4)   // float[128*8] head partials
#define SMEM_TOTAL (RED_OFF + MTILE*8*4) // 188928

__device__ __forceinline__ uint32_t s2u(const void* p) {
    uint32_t a;
    asm("{ .reg .u64 t; cvta.to.shared.u64 t, %1; cvt.u32.u64 %0, t; }" : "=r"(a) : "l"(p));
    return a;
}

#define LDSM4(r0, r1, r2, r3, addr) \
    asm volatile("ldmatrix.sync.aligned.m8n8.x4.shared.b16 {%0,%1,%2,%3}, [%4];" \
                 : "=r"(r0), "=r"(r1), "=r"(r2), "=r"(r3) : "r"(addr))

#define MMA16816(d0, d1, d2, d3, a0, a1, a2, a3, b0, b1) \
    asm volatile("mma.sync.aligned.m16n8k16.row.col.f32.f16.f16.f32 " \
                 "{%0,%1,%2,%3}, {%4,%5,%6,%7}, {%8,%9}, {%0,%1,%2,%3};" \
                 : "+f"(d0), "+f"(d1), "+f"(d2), "+f"(d3) \
                 : "r"(a0), "r"(a1), "r"(a2), "r"(a3), "r"(b0), "r"(b1))

// sigmoid(v) = 0.5 * tanh(0.5 v) + 0.5  -> single MUFU.TANH
__device__ __forceinline__ float sigmoid_f(float v) {
    float t;
    asm("tanh.approx.f32 %0, %1;" : "=f"(t) : "f"(0.5f * v));
    return fmaf(0.5f, t, 0.5f);
}

__global__ __launch_bounds__(NTHREADS, 1)
void lstm_kernel(const float* __restrict__ x, const float* __restrict__ kern,
                 const float* __restrict__ rk, const float* __restrict__ bias,
                 const float* __restrict__ Wd, const float* __restrict__ bd,
                 float* __restrict__ out) {
    extern __shared__ char smem[];
    const uint32_t base = s2u(smem);
    const int tid  = threadIdx.x;
    const int lane = tid & 31;
    const int wid  = tid >> 5;
    const int m    = wid >> 1;       // m-tile (16 rows) 0..7
    const int half = wid & 1;        // N-half
    const int t4   = lane >> 2;      // 0..7
    const int j    = lane & 3;       // 0..3
    const int r_lo = 16 * m + t4;
    const int r_hi = r_lo + 8;
    const int b0   = blockIdx.x * MTILE;

    __half* bt = (__half*)(smem + BT_OFF);
    float*  kp = (float*)(smem + KP_OFF);
    float*  bp = (float*)(smem + BP_OFF);
    float*  wd = (float*)(smem + WD_OFF);
    float*  xs = (float*)(smem + XS_OFF);
    float*  red = (float*)(smem + RED_OFF);

    // ---- init: weights -> smem ----
    // n-perm: unit u, gate g -> n = 16*(u/4) + 8*(g/2) + 2*(u%4) + (g&1)
    //   => thread j of n8-tile-pair p owns all 4 gates of unit u = 4p+j.
    // k-perm: h-index ks -> kk = (ks&3)*32 + (ks>>2)
    //   => thread j's 16 units land on 16 contiguous A columns (32B writeback).
    for (int i = tid; i < HH * GG; i += NTHREADS) {
        int ks = i >> 9, col = i & 511;
        int u = col & 127, g = col >> 7;
        int n = 16 * (u >> 2) + 8 * (g >> 1) + 2 * (u & 3) + (g & 1);
        int kk = (ks & 3) * 32 + (ks >> 2);
        bt[n * PADK + kk] = __float2half(rk[i]);
    }
    for (int col = tid; col < GG; col += NTHREADS) {
        int u = col & 127, g = col >> 7;
        kp[u * 4 + g] = kern[col];
        bp[u * 4 + g] = bias[col];
    }
    if (tid < HH) wd[tid] = Wd[tid];
    for (int i = tid; i < MTILE * TT; i += NTHREADS) xs[i] = x[(size_t)b0 * TT + i];
    for (int i = tid; i < A_BYTES / 4; i += NTHREADS) ((uint32_t*)(smem + A_OFF))[i] = 0u;
    __syncthreads();

    // ldmatrix lane addressing: row = lane%16, +16B col offset for lanes 16-31
    const uint32_t lrow = (uint32_t)((lane & 7) + (lane & 8));
    const uint32_t lcol = (uint32_t)((lane >> 4) << 4);
    const uint32_t a_base  = base + A_OFF  + (16u * m + lrow) * ROWB + lcol;
    const uint32_t bt_base = base + BT_OFF + ((uint32_t)half * 256u + lrow) * ROWB + lcol;
    // contiguous h writeback: rows r_lo/r_hi, bytes [64j + 32*half, +32)
    char* st_lo = smem + A_OFF + r_lo * ROWB + 64 * j + 32 * half;
    char* st_hi = smem + A_OFF + r_hi * ROWB + 64 * j + 32 * half;

    const float4* kp4 = (const float4*)kp;
    const float4* bp4 = (const float4*)bp;

    float c[32];
#pragma unroll
    for (int i = 0; i < 32; i++) c[i] = 0.0f;
    float ps_lo = 0.0f, ps_hi = 0.0f;
    const int bar_id = m + 1;

#pragma unroll 1
    for (int t = 0; t < TT; t++) {
        asm volatile("bar.sync %0, %1;" :: "r"(bar_id), "n"(64) : "memory");  // A ready

        uint32_t a[8][4];
#pragma unroll
        for (int kb = 0; kb < 8; kb++)
            LDSM4(a[kb][0], a[kb][1], a[kb][2], a[kb][3], a_base + kb * 32u);

        asm volatile("bar.sync %0, %1;" :: "r"(bar_id), "n"(64) : "memory");  // A consumed

        const float x_lo = xs[r_lo * TT + t];
        const float x_hi = xs[r_hi * TT + t];

        uint32_t hlo2[8], hhi2[8];
        float hp_lo = 0.f, hp_hi = 0.f;

#pragma unroll 2
        for (int pp = 0; pp < 16; pp++) {
            float d[8];
#pragma unroll
            for (int q = 0; q < 8; q++) d[q] = 0.0f;
            const uint32_t bta = bt_base + (uint32_t)pp * (16u * ROWB);
#pragma unroll
            for (int kb = 0; kb < 8; kb++) {
                uint32_t bq0, bq1, bq2, bq3;
                LDSM4(bq0, bq1, bq2, bq3, bta + kb * 32u);
                MMA16816(d[0], d[1], d[2], d[3], a[kb][0], a[kb][1], a[kb][2], a[kb][3], bq0, bq2);
                MMA16816(d[4], d[5], d[6], d[7], a[kb][0], a[kb][1], a[kb][2], a[kb][3], bq1, bq3);
            }
            const int u = 4 * (half * 16 + pp) + j;
            const float4 kv = kp4[u];
            const float4 bv = bp4[u];

            // lo row: d0=i d1=f d4=g d5=o ; hi row: d2 d3 d6 d7
            float zi = d[0] + x_lo * kv.x + bv.x;
            float zf = d[1] + x_lo * kv.y + bv.y;
            float zg = d[4] + x_lo * kv.z + bv.z;
            float zo = d[5] + x_lo * kv.w + bv.w;
            float ig = sigmoid_f(zi), fg = sigmoid_f(zf), og = sigmoid_f(zo);
            float cn = fmaf(fg, c[2 * pp], ig * fmaxf(zg, 0.0f));
            c[2 * pp] = cn;
            float h_lo = og * fmaxf(cn, 0.0f);

            zi = d[2] + x_hi * kv.x + bv.x;
            zf = d[3] + x_hi * kv.y + bv.y;
            zg = d[6] + x_hi * kv.z + bv.z;
            zo = d[7] + x_hi * kv.w + bv.w;
            ig = sigmoid_f(zi); fg = sigmoid_f(zf); og = sigmoid_f(zo);
            float cn2 = fmaf(fg, c[2 * pp + 1], ig * fmaxf(zg, 0.0f));
            c[2 * pp + 1] = cn2;
            float h_hi = og * fmaxf(cn2, 0.0f);

            if (pp & 1) {
                __half2 plo = __floats2half2_rn(hp_lo, h_lo);
                __half2 phi = __floats2half2_rn(hp_hi, h_hi);
                hlo2[pp >> 1] = *(uint32_t*)&plo;
                hhi2[pp >> 1] = *(uint32_t*)&phi;
            } else {
                hp_lo = h_lo; hp_hi = h_hi;
            }
            if (t == TT - 1) {
                ps_lo = fmaf(h_lo, wd[u], ps_lo);
                ps_hi = fmaf(h_hi, wd[u], ps_hi);
            }
        }

        // contiguous fp16 h writeback: 2 x 16B per row
        *(uint4*)(st_lo)      = make_uint4(hlo2[0], hlo2[1], hlo2[2], hlo2[3]);
        *(uint4*)(st_lo + 16) = make_uint4(hlo2[4], hlo2[5], hlo2[6], hlo2[7]);
        *(uint4*)(st_hi)      = make_uint4(hhi2[0], hhi2[1], hhi2[2], hhi2[3]);
        *(uint4*)(st_hi + 16) = make_uint4(hhi2[4], hhi2[5], hhi2[6], hhi2[7]);
    }

    // ---- output head: y = h_T . Wd + bd ----
    red[r_lo * 8 + half * 4 + j] = ps_lo;
    red[r_hi * 8 + half * 4 + j] = ps_hi;
    __syncthreads();
    if (tid < MTILE) {
        const float* p = red + tid * 8;
        float s = ((p[0] + p[1]) + (p[2] + p[3])) + ((p[4] + p[5]) + (p[6] + p[7]));
        out[b0 + tid] = s + bd[0];
    }
}

extern "C" void kernel_launch(void* const* d_in, const int* in_sizes, int n_in,
                              void* d_out, int out_size) {
    const float* x    = (const float*)d_in[0];
    const float* kern = (const float*)d_in[1];
    const float* rk   = (const float*)d_in[2];
    const float* bias = (const float*)d_in[3];
    const float* Wd   = (const float*)d_in[4];
    const float* bd   = (const float*)d_in[5];
    float* out = (float*)d_out;

    int B = in_sizes[0] / TT;        // 65536
    int grid = B / MTILE;            // 512

    cudaFuncSetAttribute(lstm_kernel, cudaFuncAttributeMaxDynamicSharedMemorySize, SMEM_TOTAL);
    lstm_kernel<<<grid, NTHREADS, SMEM_TOTAL>>>(x, kern, rk, bias, Wd, bd, out);
}